// round 14
// baseline (speedup 1.0000x reference)
#include <cuda_runtime.h>
#include <cuda_fp16.h>
#include <math.h>
#include <stdint.h>

// Problem constants
#define D_DIM   512
#define V_DIM   32000
#define BS_ROWS 2048
#define GAMMA_F 0.5f
#define EPS_F   1e-12f

// GEMM tiling: CTA 128x160, 8 warps (warp tile 32x80), persistent 2 CTAs/SM
#define MT 128
#define NT 160
#define KC 64               // fp16 K per chunk (128 B rows)
#define NCHUNK 8            // 512 / 64
#define NSTAGE 3
#define NTM 16              // tiles along M
#define NTN 200             // tiles along N
#define NTILES (NTM * NTN)  // 3200
#define GRIDP 296           // 148 SMs * 2 CTAs

// SMEM: 128B rows with XOR swizzle (chunk ^= row&7) -> conflict-free ldmatrix
#define ROWB   128
#define A_OFF  0
#define B_OFF  (MT * ROWB)               // 16384
#define STAGE  ((MT + NT) * ROWB)        // 36864
#define V_OFF  (NSTAGE * STAGE)          // 110592 : vinv double buffer (2*160 f32)
#define SMEMSZ (V_OFF + 2 * NT * 4)      // 111872

// ---------------------------------------------------------------------------
// Static scratch
// ---------------------------------------------------------------------------
__device__ __half g_qh[BS_ROWS * D_DIM];
__device__ __half g_eh[(size_t)V_DIM * D_DIM];
__device__ float              g_vinv[V_DIM];
__device__ float              g_outn[BS_ROWS * D_DIM];
__device__ unsigned long long g_best[BS_ROWS];
__device__ float              g_diff[BS_ROWS];
__device__ int                g_cnt;     // zero-initialized; self-resetting

// ---------------------------------------------------------------------------
// helpers
// ---------------------------------------------------------------------------
__device__ __forceinline__ uint32_t smem_u32(const void* p) {
    uint32_t a;
    asm("{ .reg .u64 t; cvta.to.shared.u64 t, %1; cvt.u32.u64 %0, t; }" : "=r"(a) : "l"(p));
    return a;
}
__device__ __forceinline__ void cp16(uint32_t dst, const void* src) {
    asm volatile("cp.async.cg.shared.global [%0], [%1], 16;" :: "r"(dst), "l"(src));
}
#define CP_COMMIT() asm volatile("cp.async.commit_group;" ::: "memory")
#define CP_WAIT1()  asm volatile("cp.async.wait_group 1;" ::: "memory")
#define CP_WAIT0()  asm volatile("cp.async.wait_group 0;" ::: "memory")

__device__ __forceinline__ void ldsm_x4(uint32_t addr, uint32_t& r0, uint32_t& r1,
                                        uint32_t& r2, uint32_t& r3) {
    asm volatile("ldmatrix.sync.aligned.m8n8.x4.shared.b16 {%0,%1,%2,%3}, [%4];"
                 : "=r"(r0), "=r"(r1), "=r"(r2), "=r"(r3) : "r"(addr));
}
__device__ __forceinline__ void mma16816(float* c, const uint32_t* a, const uint32_t* b) {
    asm volatile(
        "mma.sync.aligned.m16n8k16.row.col.f32.f16.f16.f32 "
        "{%0,%1,%2,%3}, {%4,%5,%6,%7}, {%8,%9}, {%0,%1,%2,%3};"
        : "+f"(c[0]), "+f"(c[1]), "+f"(c[2]), "+f"(c[3])
        : "r"(a[0]), "r"(a[1]), "r"(a[2]), "r"(a[3]), "r"(b[0]), "r"(b[1]));
}

// XOR swizzle: 16B chunk index within a 128B row, xored with row&7
__device__ __forceinline__ uint32_t swz(uint32_t row, uint32_t chunk) {
    return row * ROWB + ((chunk ^ (row & 7u)) << 4);
}

// pack 4 floats -> 4 halves in a uint2 (8B)
__device__ __forceinline__ uint2 pack_h4(float4 v) {
    __half2 lo = __halves2half2(__float2half_rn(v.x), __float2half_rn(v.y));
    __half2 hi = __halves2half2(__float2half_rn(v.z), __float2half_rn(v.w));
    uint2 r;
    r.x = *(uint32_t*)&lo;
    r.y = *(uint32_t*)&hi;
    return r;
}

// Monotone (score, idx) packing; bigger score wins, tie -> smaller index
__device__ __forceinline__ unsigned long long enc_key(float v, unsigned idx) {
    unsigned u = __float_as_uint(v);
    u = (u & 0x80000000u) ? ~u : (u | 0x80000000u);
    return ((unsigned long long)u << 32) | (unsigned long long)(0x7fffffffu - idx);
}
__device__ __forceinline__ int clamp_idx(int t) {
    t = t < 0 ? 0 : t;
    return t >= V_DIM ? V_DIM - 1 : t;
}

// ---------------------------------------------------------------------------
// Kernel 1 (merged): blocks [0,2000) = vocab pass (2 rows per warp);
// blocks [2000,2512) = preds transpose + q build (ST=4, ~11KB smem).
// ---------------------------------------------------------------------------
#define ST 4
#define VBLKS (V_DIM / 16)    // 2000 blocks * 8 warps * 2 rows = 32000
#define PBLKS (BS_ROWS / ST)  // 512
__global__ void __launch_bounds__(256, 6) pre_kernel(const float* __restrict__ emb,
                                                     const float* __restrict__ preds,
                                                     const int* __restrict__ target) {
    __shared__ float tile[D_DIM][ST + 1];   // 10240 B, prep role only
    __shared__ float part[64][ST + 1];
    __shared__ float inv_s[ST];
    __shared__ int   tgt_s[ST];

    if (blockIdx.x < VBLKS) {
        // ------- vocab role: each warp handles rows r0, r0+1 -------
        int warp = (blockIdx.x * 256 + threadIdx.x) >> 5;
        int lane = threadIdx.x & 31;
        int r0 = warp * 2;
        const float4* rowA = (const float4*)(emb + (size_t)r0 * D_DIM);
        const float4* rowB = (const float4*)(emb + (size_t)(r0 + 1) * D_DIM);

        float sa = 0.f, sb = 0.f;
#pragma unroll
        for (int k = 0; k < 4; k++) {
            float4 va = __ldcs(&rowA[lane + 32 * k]);
            float4 vb = __ldcs(&rowB[lane + 32 * k]);
            sa = fmaf(va.x, va.x, sa); sa = fmaf(va.y, va.y, sa);
            sa = fmaf(va.z, va.z, sa); sa = fmaf(va.w, va.w, sa);
            sb = fmaf(vb.x, vb.x, sb); sb = fmaf(vb.y, vb.y, sb);
            sb = fmaf(vb.z, vb.z, sb); sb = fmaf(vb.w, vb.w, sb);
            size_t ea = (size_t)r0 * D_DIM + (lane + 32 * k) * 4;
            *(uint2*)(g_eh + ea)         = pack_h4(va);
            *(uint2*)(g_eh + ea + D_DIM) = pack_h4(vb);
        }
#pragma unroll
        for (int off = 16; off; off >>= 1) {
            sa += __shfl_xor_sync(0xffffffffu, sa, off);
            sb += __shfl_xor_sync(0xffffffffu, sb, off);
        }
        if (lane == 0) {
            g_vinv[r0]     = 1.f / fmaxf(sqrtf(sa), EPS_F);
            g_vinv[r0 + 1] = 1.f / fmaxf(sqrtf(sb), EPS_F);
        }
        return;
    }

    // ------- prep role: single global pass, smem-staged transpose -------
    int blk = blockIdx.x - VBLKS;       // 0..511
    int b   = blk >> 7;                 // 4 batches x 128 s-tiles
    int s0  = (blk & 127) * ST;
    int t   = threadIdx.x;
    const float* P = preds + (size_t)b * D_DIM * 512 + s0;

    int ss = t & 3, dr = t >> 2;        // ss 0..3, dr 0..63
#pragma unroll
    for (int d0 = 0; d0 < D_DIM; d0 += 64)
        tile[d0 + dr][ss] = P[(size_t)(d0 + dr) * 512 + ss];
    __syncthreads();

    float acc = 0.f;
#pragma unroll
    for (int d0 = 0; d0 < D_DIM; d0 += 64)
        { float x = tile[d0 + dr][ss]; acc = fmaf(x, x, acc); }
    part[dr][ss] = acc;
    __syncthreads();
    if (t < ST) {
        float n = 0.f;
#pragma unroll
        for (int i = 0; i < 64; i++) n += part[i][t];
        inv_s[t] = 1.f / fmaxf(sqrtf(n), EPS_F);
        int r = b * 512 + s0 + t;
        tgt_s[t] = clamp_idx(target[r]);
        g_best[r] = 0ull;
    }
    __syncthreads();

    int ss2  = t >> 6;                  // 0..3
    int dcol = (t & 63) * 4;            // 0..252 step 4
    float inv = inv_s[ss2];
    int r = b * 512 + s0 + ss2;
    const float* erow = emb + (size_t)tgt_s[ss2] * D_DIM;
#pragma unroll
    for (int d0 = 0; d0 < D_DIM; d0 += 256) {
        float4 o;
        __half hq[4];
        float* ov = &o.x;
#pragma unroll
        for (int j = 0; j < 4; j++) {
            float on = tile[d0 + dcol + j][ss2] * inv;
            ov[j] = on;
            hq[j] = __float2half_rn(on - erow[d0 + dcol + j]);
        }
        *(float4*)(g_outn + (size_t)r * D_DIM + d0 + dcol) = o;
        *(__half2*)(g_qh + (size_t)r * D_DIM + d0 + dcol)     = __halves2half2(hq[0], hq[1]);
        *(__half2*)(g_qh + (size_t)r * D_DIM + d0 + dcol + 2) = __halves2half2(hq[2], hq[3]);
    }
}

// ---------------------------------------------------------------------------
// Kernel 2: PERSISTENT fp16 mma.sync GEMM. 296 CTAs, each walks tiles
// bid, bid+296, ... The 3-stage cp.async ring is indexed by a global chunk
// sequence that crosses tile boundaries (pipeline primed once per CTA).
// vinv prefetched per tile into a double-buffered smem slot via cp.async.
// ---------------------------------------------------------------------------
__global__ void __launch_bounds__(256, 2) gemm_mma_kernel() {
    extern __shared__ char smem[];
    const uint32_t sb = smem_u32(smem);
    const int tid  = threadIdx.x;
    const int wid  = tid >> 5;
    const int lane = tid & 31;
    const int bid  = blockIdx.x;
    const int warp_m = (wid & 3) * 32;      // 4 warps along M
    const int warp_n = (wid >> 2) * 80;     // 2 warps along N

    const int ntile = (NTILES - bid + GRIDP - 1) / GRIDP;   // 10 or 11
    const int total = ntile * NCHUNK;

    // issue all cp.async for global chunk g (tile-local tl = g/8, ch = g%8)
    auto issue = [&](int g) {
        int tl   = g >> 3, ch = g & 7;
        int tile = bid + tl * GRIDP;
        int mblk = (tile & (NTM - 1)) * MT;
        int nblk = (tile >> 4) * NT;
        const __half* Aq = g_qh + (size_t)mblk * D_DIM;
        const __half* Be = g_eh + (size_t)nblk * D_DIM;
        int kc = ch * KC;
        uint32_t st = sb + (g % NSTAGE) * STAGE;
#pragma unroll
        for (int i = 0; i < 4; i++) {
            int s = tid + i * 256;
            int row = s >> 3, c = s & 7;
            cp16(st + A_OFF + swz(row, c), Aq + (size_t)row * D_DIM + kc + c * 8);
        }
#pragma unroll
        for (int i = 0; i < 5; i++) {
            int s = tid + i * 256;
            int row = s >> 3, c = s & 7;
            cp16(st + B_OFF + swz(row, c), Be + (size_t)row * D_DIM + kc + c * 8);
        }
        if (ch == 0 && tid < 40)   // vinv for this tile -> buffer tl&1
            cp16(sb + V_OFF + (tl & 1) * (NT * 4) + tid * 16, g_vinv + nblk + tid * 4);
    };

    float acc[2][10][4];
#pragma unroll
    for (int i = 0; i < 2; i++)
#pragma unroll
        for (int j = 0; j < 10; j++)
#pragma unroll
            for (int k = 0; k < 4; k++) acc[i][j][k] = 0.f;

    issue(0); CP_COMMIT();
    issue(1); CP_COMMIT();

    for (int g = 0; g < total; g++) {
        if (g + 1 < total) { CP_WAIT1(); } else { CP_WAIT0(); }
        __syncthreads();   // chunk g resident for all warps; slot g+2 free

        if (g + 2 < total) {
            issue(g + 2);
            CP_COMMIT();
        }

        uint32_t st  = sb + (g % NSTAGE) * STAGE;
        uint32_t sa  = st + A_OFF;
        uint32_t sbm = st + B_OFF;
#pragma unroll
        for (int ks = 0; ks < 4; ks++) {
            int k = ks * 16;
            uint32_t a[2][4];
#pragma unroll
            for (int mi = 0; mi < 2; mi++) {
                int row = warp_m + mi * 16 + (lane & 15);
                int kch = (k >> 3) + (lane >> 4);
                ldsm_x4(sa + swz(row, kch), a[mi][0], a[mi][1], a[mi][2], a[mi][3]);
            }
#pragma unroll
            for (int bj = 0; bj < 5; bj++) {
                uint32_t b0[2], b1[2];
                int n   = warp_n + bj * 16 + (lane & 7) + ((lane >> 4) & 1) * 8;
                int kch = (k >> 3) + ((lane >> 3) & 1);
                ldsm_x4(sbm + swz(n, kch), b0[0], b0[1], b1[0], b1[1]);
#pragma unroll
                for (int mi = 0; mi < 2; mi++) {
                    mma16816(acc[mi][bj * 2],     a[mi], b0);
                    mma16816(acc[mi][bj * 2 + 1], a[mi], b1);
                }
            }
        }

        if ((g & 7) == 7) {
            // ---- epilogue for tile tl = g>>3 (registers + smem vinv only) ----
            int tl   = g >> 3;
            int tile = bid + tl * GRIDP;
            int mblk = (tile & (NTM - 1)) * MT;
            int nblk = (tile >> 4) * NT;
            const float* vin = (const float*)(smem + V_OFF + (tl & 1) * (NT * 4));
#pragma unroll
            for (int mi = 0; mi < 2; mi++) {
                float bv0 = -1e30f, bv1 = -1e30f;
                int   bj0 = 0,      bj1 = 0;
#pragma unroll
                for (int nj = 0; nj < 10; nj++) {
                    int c0 = warp_n + nj * 8 + 2 * (lane & 3);
                    float v00 = acc[mi][nj][0] * vin[c0];
                    float v01 = acc[mi][nj][1] * vin[c0 + 1];
                    float v10 = acc[mi][nj][2] * vin[c0];
                    float v11 = acc[mi][nj][3] * vin[c0 + 1];
                    if (v00 > bv0) { bv0 = v00; bj0 = c0; }
                    if (v01 > bv0) { bv0 = v01; bj0 = c0 + 1; }
                    if (v10 > bv1) { bv1 = v10; bj1 = c0; }
                    if (v11 > bv1) { bv1 = v11; bj1 = c0 + 1; }
                }
#pragma unroll
                for (int off = 1; off < 4; off <<= 1) {
                    float o0 = __shfl_xor_sync(0xffffffffu, bv0, off);
                    int   j0 = __shfl_xor_sync(0xffffffffu, bj0, off);
                    float o1 = __shfl_xor_sync(0xffffffffu, bv1, off);
                    int   j1 = __shfl_xor_sync(0xffffffffu, bj1, off);
                    if (o0 > bv0 || (o0 == bv0 && j0 < bj0)) { bv0 = o0; bj0 = j0; }
                    if (o1 > bv1 || (o1 == bv1 && j1 < bj1)) { bv1 = o1; bj1 = j1; }
                }
                if ((lane & 3) == 0) {
                    int r0 = mblk + warp_m + mi * 16 + (lane >> 2);
                    atomicMax(&g_best[r0],     enc_key(bv0, (unsigned)(nblk + bj0)));
                    atomicMax(&g_best[r0 + 8], enc_key(bv1, (unsigned)(nblk + bj1)));
                }
            }
            // reset accumulators for next tile
#pragma unroll
            for (int i = 0; i < 2; i++)
#pragma unroll
                for (int j = 0; j < 10; j++)
#pragma unroll
                    for (int k2 = 0; k2 < 4; k2++) acc[i][j][k2] = 0.f;
        }
    }
}

// ---------------------------------------------------------------------------
// Kernel 3: per-row hinge (warp/row, float4 gathers) + last-block reduction.
// ---------------------------------------------------------------------------
__global__ void __launch_bounds__(256) finalize_reduce_kernel(
        const float* __restrict__ emb,
        const int* __restrict__ target,
        const int* __restrict__ pad,
        float* __restrict__ out) {
    __shared__ int s_last;
    int r    = blockIdx.x * 8 + (threadIdx.x >> 5);
    int lane = threadIdx.x & 31;
    int t = clamp_idx(target[r]);
    unsigned long long key = g_best[r];
    int jm = clamp_idx((int)(0x7fffffffu - (unsigned)(key & 0xffffffffu)));

    const float4* on = (const float4*)(g_outn + (size_t)r * D_DIM);
    const float4* e1 = (const float4*)(emb + (size_t)t  * D_DIM);
    const float4* e2 = (const float4*)(emb + (size_t)jm * D_DIM);
    float d1 = 0.f, d2 = 0.f;
#pragma unroll
    for (int i = 0; i < 4; i++) {
        int idx = lane + i * 32;
        float4 o = on[idx], a = __ldg(&e1[idx]), b2 = __ldg(&e2[idx]);
        d1 = fmaf(o.x, a.x, d1);  d1 = fmaf(o.y, a.y, d1);
        d1 = fmaf(o.z, a.z, d1);  d1 = fmaf(o.w, a.w, d1);
        d2 = fmaf(o.x, b2.x, d2); d2 = fmaf(o.y, b2.y, d2);
        d2 = fmaf(o.z, b2.z, d2); d2 = fmaf(o.w, b2.w, d2);
    }
#pragma unroll
    for (int off = 16; off; off >>= 1) {
        d1 += __shfl_xor_sync(0xffffffffu, d1, off);
        d2 += __shfl_xor_sync(0xffffffffu, d2, off);
    }
    if (lane == 0) {
        d1 *= g_vinv[t];
        d2 *= g_vinv[jm];
        float df = fmaxf(GAMMA_F + d2 - d1, 0.f);
        g_diff[r] = (target[r] != *pad) ? df : 0.f;
    }
    __threadfence();
    __syncthreads();
    if (threadIdx.x == 0)
        s_last = (atomicAdd(&g_cnt, 1) == (int)gridDim.x - 1) ? 1 : 0;
    __syncthreads();
    if (!s_last) return;

    __shared__ float ssum[256];
    __shared__ float scnt[256];
    int tt = threadIdx.x;
    int p = *pad;
    float s = 0.f, c = 0.f;
    for (int rr = tt; rr < BS_ROWS; rr += 256) {
        s += g_diff[rr];
        c += (target[rr] != p) ? 1.f : 0.f;
    }
    ssum[tt] = s; scnt[tt] = c; __syncthreads();
    for (int off = 128; off; off >>= 1) {
        if (tt < off) { ssum[tt] += ssum[tt + off]; scnt[tt] += scnt[tt + off]; }
        __syncthreads();
    }
    if (tt == 0) {
        out[0] = ssum[0] / scnt[0];
        g_cnt = 0;   // self-reset for next graph replay
    }
}

// ---------------------------------------------------------------------------
extern "C" void kernel_launch(void* const* d_in, const int* in_sizes, int n_in,
                              void* d_out, int out_size) {
    const float* preds  = (const float*)d_in[0];
    const float* emb    = (const float*)d_in[1];
    const int*   target = (const int*)d_in[2];
    const int*   pad    = (const int*)d_in[3];

    cudaFuncSetAttribute(gemm_mma_kernel, cudaFuncAttributeMaxDynamicSharedMemorySize, SMEMSZ);

    pre_kernel<<<VBLKS + PBLKS, 256>>>(emb, preds, target);
    gemm_mma_kernel<<<GRIDP, 256, SMEMSZ>>>();
    finalize_reduce_kernel<<<BS_ROWS / 8, 256>>>(emb, target, pad, (float*)d_out);
}

// round 15
// speedup vs baseline: 1.0078x; 1.0078x over previous
#include <cuda_runtime.h>
#include <cuda_fp16.h>
#include <math.h>
#include <stdint.h>

// Problem constants
#define D_DIM   512
#define V_DIM   32000
#define BS_ROWS 2048
#define GAMMA_F 0.5f
#define EPS_F   1e-12f

// GEMM tiling: CTA 128x160, 8 warps (warp tile 32x80), 2 CTAs/SM
#define MT 128
#define NT 160
#define KC 64               // fp16 K per chunk (128 B rows)
#define NCHUNK 8            // 512 / 64
#define NSTAGE 3

// SMEM: 128B rows with XOR swizzle (chunk ^= row&7) -> conflict-free ldmatrix
#define ROWB   128
#define A_OFF  0
#define B_OFF  (MT * ROWB)               // 16384
#define STAGE  ((MT + NT) * ROWB)        // 36864
#define V_OFF  (NSTAGE * STAGE)          // 110592 : vinv staging (160 floats)
#define SMEMSZ (V_OFF + NT * 4)          // 111232

// ---------------------------------------------------------------------------
// Static scratch
// ---------------------------------------------------------------------------
__device__ __half g_qh[BS_ROWS * D_DIM];
__device__ __half g_eh[(size_t)V_DIM * D_DIM];
__device__ float              g_vinv[V_DIM];
__device__ float              g_outn[BS_ROWS * D_DIM];
__device__ float              g_d1[BS_ROWS];     // raw dot out_norm . emb[target]
__device__ unsigned long long g_best[BS_ROWS];
__device__ float              g_diff[BS_ROWS];
__device__ int                g_cnt;     // zero-initialized; self-resetting

// ---------------------------------------------------------------------------
// helpers
// ---------------------------------------------------------------------------
__device__ __forceinline__ uint32_t smem_u32(const void* p) {
    uint32_t a;
    asm("{ .reg .u64 t; cvta.to.shared.u64 t, %1; cvt.u32.u64 %0, t; }" : "=r"(a) : "l"(p));
    return a;
}
__device__ __forceinline__ void cp16(uint32_t dst, const void* src) {
    asm volatile("cp.async.cg.shared.global [%0], [%1], 16;" :: "r"(dst), "l"(src));
}
#define CP_COMMIT() asm volatile("cp.async.commit_group;" ::: "memory")
#define CP_WAIT1()  asm volatile("cp.async.wait_group 1;" ::: "memory")
#define CP_WAIT0()  asm volatile("cp.async.wait_group 0;" ::: "memory")

__device__ __forceinline__ void ldsm_x4(uint32_t addr, uint32_t& r0, uint32_t& r1,
                                        uint32_t& r2, uint32_t& r3) {
    asm volatile("ldmatrix.sync.aligned.m8n8.x4.shared.b16 {%0,%1,%2,%3}, [%4];"
                 : "=r"(r0), "=r"(r1), "=r"(r2), "=r"(r3) : "r"(addr));
}
__device__ __forceinline__ void mma16816(float* c, const uint32_t* a, const uint32_t* b) {
    asm volatile(
        "mma.sync.aligned.m16n8k16.row.col.f32.f16.f16.f32 "
        "{%0,%1,%2,%3}, {%4,%5,%6,%7}, {%8,%9}, {%0,%1,%2,%3};"
        : "+f"(c[0]), "+f"(c[1]), "+f"(c[2]), "+f"(c[3])
        : "r"(a[0]), "r"(a[1]), "r"(a[2]), "r"(a[3]), "r"(b[0]), "r"(b[1]));
}

// XOR swizzle: 16B chunk index within a 128B row, xored with row&7
__device__ __forceinline__ uint32_t swz(uint32_t row, uint32_t chunk) {
    return row * ROWB + ((chunk ^ (row & 7u)) << 4);
}

// pack 4 floats -> 4 halves in a uint2 (8B)
__device__ __forceinline__ uint2 pack_h4(float4 v) {
    __half2 lo = __halves2half2(__float2half_rn(v.x), __float2half_rn(v.y));
    __half2 hi = __halves2half2(__float2half_rn(v.z), __float2half_rn(v.w));
    uint2 r;
    r.x = *(uint32_t*)&lo;
    r.y = *(uint32_t*)&hi;
    return r;
}

// Monotone (score, idx) packing; bigger score wins, tie -> smaller index
__device__ __forceinline__ unsigned long long enc_key(float v, unsigned idx) {
    unsigned u = __float_as_uint(v);
    u = (u & 0x80000000u) ? ~u : (u | 0x80000000u);
    return ((unsigned long long)u << 32) | (unsigned long long)(0x7fffffffu - idx);
}
__device__ __forceinline__ int clamp_idx(int t) {
    t = t < 0 ? 0 : t;
    return t >= V_DIM ? V_DIM - 1 : t;
}

// ---------------------------------------------------------------------------
// Kernel 1 (merged): blocks [0,2000) = vocab pass (2 rows per warp);
// blocks [2000,2512) = preds transpose + q build + d1 dot (ST=4).
// ---------------------------------------------------------------------------
#define ST 4
#define VBLKS (V_DIM / 16)    // 2000 blocks * 8 warps * 2 rows = 32000
#define PBLKS (BS_ROWS / ST)  // 512
__global__ void __launch_bounds__(256, 6) pre_kernel(const float* __restrict__ emb,
                                                     const float* __restrict__ preds,
                                                     const int* __restrict__ target) {
    __shared__ float tile[D_DIM][ST + 1];   // 10240 B, prep role only
    __shared__ float part[64][ST + 1];
    __shared__ float inv_s[ST];
    __shared__ int   tgt_s[ST];
    __shared__ float dpart[8];              // 2 warps per row partials

    if (blockIdx.x < VBLKS) {
        // ------- vocab role: each warp handles rows r0, r0+1 -------
        int warp = (blockIdx.x * 256 + threadIdx.x) >> 5;
        int lane = threadIdx.x & 31;
        int r0 = warp * 2;
        const float4* rowA = (const float4*)(emb + (size_t)r0 * D_DIM);
        const float4* rowB = (const float4*)(emb + (size_t)(r0 + 1) * D_DIM);

        float sa = 0.f, sb = 0.f;
#pragma unroll
        for (int k = 0; k < 4; k++) {
            float4 va = __ldcs(&rowA[lane + 32 * k]);
            float4 vb = __ldcs(&rowB[lane + 32 * k]);
            sa = fmaf(va.x, va.x, sa); sa = fmaf(va.y, va.y, sa);
            sa = fmaf(va.z, va.z, sa); sa = fmaf(va.w, va.w, sa);
            sb = fmaf(vb.x, vb.x, sb); sb = fmaf(vb.y, vb.y, sb);
            sb = fmaf(vb.z, vb.z, sb); sb = fmaf(vb.w, vb.w, sb);
            size_t ea = (size_t)r0 * D_DIM + (lane + 32 * k) * 4;
            *(uint2*)(g_eh + ea)         = pack_h4(va);
            *(uint2*)(g_eh + ea + D_DIM) = pack_h4(vb);
        }
#pragma unroll
        for (int off = 16; off; off >>= 1) {
            sa += __shfl_xor_sync(0xffffffffu, sa, off);
            sb += __shfl_xor_sync(0xffffffffu, sb, off);
        }
        if (lane == 0) {
            g_vinv[r0]     = 1.f / fmaxf(sqrtf(sa), EPS_F);
            g_vinv[r0 + 1] = 1.f / fmaxf(sqrtf(sb), EPS_F);
        }
        return;
    }

    // ------- prep role: single global pass, smem-staged transpose -------
    int blk = blockIdx.x - VBLKS;       // 0..511
    int b   = blk >> 7;                 // 4 batches x 128 s-tiles
    int s0  = (blk & 127) * ST;
    int t   = threadIdx.x;
    const float* P = preds + (size_t)b * D_DIM * 512 + s0;

    int ss = t & 3, dr = t >> 2;        // ss 0..3, dr 0..63
#pragma unroll
    for (int d0 = 0; d0 < D_DIM; d0 += 64)
        tile[d0 + dr][ss] = P[(size_t)(d0 + dr) * 512 + ss];
    __syncthreads();

    float acc = 0.f;
#pragma unroll
    for (int d0 = 0; d0 < D_DIM; d0 += 64)
        { float x = tile[d0 + dr][ss]; acc = fmaf(x, x, acc); }
    part[dr][ss] = acc;
    __syncthreads();
    if (t < ST) {
        float n = 0.f;
#pragma unroll
        for (int i = 0; i < 64; i++) n += part[i][t];
        inv_s[t] = 1.f / fmaxf(sqrtf(n), EPS_F);
        int r = b * 512 + s0 + t;
        tgt_s[t] = clamp_idx(target[r]);
        g_best[r] = 0ull;
    }
    __syncthreads();

    int ss2  = t >> 6;                  // 0..3
    int dcol = (t & 63) * 4;            // 0..252 step 4
    float inv = inv_s[ss2];
    int r = b * 512 + s0 + ss2;
    const float* erow = emb + (size_t)tgt_s[ss2] * D_DIM;
    float dot = 0.f;
#pragma unroll
    for (int d0 = 0; d0 < D_DIM; d0 += 256) {
        float4 o;
        __half hq[4];
        float* ov = &o.x;
#pragma unroll
        for (int j = 0; j < 4; j++) {
            float e  = erow[d0 + dcol + j];
            float on = tile[d0 + dcol + j][ss2] * inv;
            ov[j] = on;
            hq[j] = __float2half_rn(on - e);
            dot = fmaf(on, e, dot);
        }
        *(float4*)(g_outn + (size_t)r * D_DIM + d0 + dcol) = o;
        *(__half2*)(g_qh + (size_t)r * D_DIM + d0 + dcol)     = __halves2half2(hq[0], hq[1]);
        *(__half2*)(g_qh + (size_t)r * D_DIM + d0 + dcol + 2) = __halves2half2(hq[2], hq[3]);
    }
    // reduce dot across the 64 threads (2 warps) of row ss2
#pragma unroll
    for (int off = 16; off; off >>= 1) dot += __shfl_xor_sync(0xffffffffu, dot, off);
    if ((t & 31) == 0) dpart[t >> 5] = dot;
    __syncthreads();
    if (t < ST) g_d1[b * 512 + s0 + t] = dpart[2 * t] + dpart[2 * t + 1];
}

// ---------------------------------------------------------------------------
// Kernel 2: fp16 mma.sync GEMM, 3-stage cp.async (1 barrier/chunk), 2 CTAs/SM,
// XOR-swizzled SMEM, vinv prefetched pre-loop, fused argmax epilogue.
// CTA 128x160, warp tile 32x80. (R13 configuration — prediction-matched.)
// ---------------------------------------------------------------------------
__global__ void __launch_bounds__(256, 2) gemm_mma_kernel() {
    extern __shared__ char smem[];
    const uint32_t sb = smem_u32(smem);
    const int tid  = threadIdx.x;
    const int wid  = tid >> 5;
    const int lane = tid & 31;
    const int mblk = blockIdx.x * MT;
    const int nblk = blockIdx.y * NT;
    const int warp_m = (wid & 3) * 32;      // 4 warps along M
    const int warp_n = (wid >> 2) * 80;     // 2 warps along N

    const __half* Aqh = g_qh + (size_t)mblk * D_DIM;
    const __half* Beh = g_eh + (size_t)nblk * D_DIM;

    if (tid < NT) ((float*)(smem + V_OFF))[tid] = g_vinv[nblk + tid];

    auto load_chunk = [&](int slot, int ch) {
        int kc = ch * KC;
        uint32_t st = sb + slot * STAGE;
#pragma unroll
        for (int i = 0; i < 4; i++) {
            int s = tid + i * 256;
            int row = s >> 3, c = s & 7;
            cp16(st + A_OFF + swz(row, c), Aqh + (size_t)row * D_DIM + kc + c * 8);
        }
#pragma unroll
        for (int i = 0; i < 5; i++) {
            int s = tid + i * 256;
            int row = s >> 3, c = s & 7;
            cp16(st + B_OFF + swz(row, c), Beh + (size_t)row * D_DIM + kc + c * 8);
        }
    };

    float acc[2][10][4];
#pragma unroll
    for (int i = 0; i < 2; i++)
#pragma unroll
        for (int j = 0; j < 10; j++)
#pragma unroll
            for (int k = 0; k < 4; k++) acc[i][j][k] = 0.f;

    load_chunk(0, 0); CP_COMMIT();
    load_chunk(1, 1); CP_COMMIT();

    for (int it = 0; it < NCHUNK; it++) {
        if (it + 1 < NCHUNK) { CP_WAIT1(); } else { CP_WAIT0(); }
        __syncthreads();

        if (it + 2 < NCHUNK) {
            load_chunk((it + 2) % NSTAGE, it + 2);
            CP_COMMIT();
        }

        uint32_t st  = sb + (it % NSTAGE) * STAGE;
        uint32_t sa  = st + A_OFF;
        uint32_t sbm = st + B_OFF;
#pragma unroll
        for (int ks = 0; ks < 4; ks++) {
            int k = ks * 16;
            uint32_t a[2][4];
#pragma unroll
            for (int mi = 0; mi < 2; mi++) {
                int row = warp_m + mi * 16 + (lane & 15);
                int kch = (k >> 3) + (lane >> 4);
                ldsm_x4(sa + swz(row, kch), a[mi][0], a[mi][1], a[mi][2], a[mi][3]);
            }
#pragma unroll
            for (int bj = 0; bj < 5; bj++) {
                uint32_t b0[2], b1[2];
                int n   = warp_n + bj * 16 + (lane & 7) + ((lane >> 4) & 1) * 8;
                int kch = (k >> 3) + ((lane >> 3) & 1);
                ldsm_x4(sbm + swz(n, kch), b0[0], b0[1], b1[0], b1[1]);
#pragma unroll
                for (int mi = 0; mi < 2; mi++) {
                    mma16816(acc[mi][bj * 2],     a[mi], b0);
                    mma16816(acc[mi][bj * 2 + 1], a[mi], b1);
                }
            }
        }
    }
    const float* vin = (const float*)(smem + V_OFF);

#pragma unroll
    for (int mi = 0; mi < 2; mi++) {
        float bv0 = -1e30f, bv1 = -1e30f;
        int   bj0 = 0,      bj1 = 0;
#pragma unroll
        for (int nj = 0; nj < 10; nj++) {
            int c0 = warp_n + nj * 8 + 2 * (lane & 3);
            float v00 = acc[mi][nj][0] * vin[c0];
            float v01 = acc[mi][nj][1] * vin[c0 + 1];
            float v10 = acc[mi][nj][2] * vin[c0];
            float v11 = acc[mi][nj][3] * vin[c0 + 1];
            if (v00 > bv0) { bv0 = v00; bj0 = c0; }
            if (v01 > bv0) { bv0 = v01; bj0 = c0 + 1; }
            if (v10 > bv1) { bv1 = v10; bj1 = c0; }
            if (v11 > bv1) { bv1 = v11; bj1 = c0 + 1; }
        }
#pragma unroll
        for (int off = 1; off < 4; off <<= 1) {
            float o0 = __shfl_xor_sync(0xffffffffu, bv0, off);
            int   j0 = __shfl_xor_sync(0xffffffffu, bj0, off);
            float o1 = __shfl_xor_sync(0xffffffffu, bv1, off);
            int   j1 = __shfl_xor_sync(0xffffffffu, bj1, off);
            if (o0 > bv0 || (o0 == bv0 && j0 < bj0)) { bv0 = o0; bj0 = j0; }
            if (o1 > bv1 || (o1 == bv1 && j1 < bj1)) { bv1 = o1; bj1 = j1; }
        }
        if ((lane & 3) == 0) {
            int r0 = mblk + warp_m + mi * 16 + (lane >> 2);
            atomicMax(&g_best[r0],     enc_key(bv0, (unsigned)(nblk + bj0)));
            atomicMax(&g_best[r0 + 8], enc_key(bv1, (unsigned)(nblk + bj1)));
        }
    }
}

// ---------------------------------------------------------------------------
// Kernel 3: per-row hinge (warp/row; only the jmax gather remains — d1 was
// precomputed in prep) + last-block scalar reduction.
// ---------------------------------------------------------------------------
__global__ void __launch_bounds__(256) finalize_reduce_kernel(
        const float* __restrict__ emb,
        const int* __restrict__ target,
        const int* __restrict__ pad,
        float* __restrict__ out) {
    __shared__ int s_last;
    int r    = blockIdx.x * 8 + (threadIdx.x >> 5);
    int lane = threadIdx.x & 31;
    int t = clamp_idx(target[r]);
    unsigned long long key = g_best[r];
    int jm = clamp_idx((int)(0x7fffffffu - (unsigned)(key & 0xffffffffu)));

    const float4* on = (const float4*)(g_outn + (size_t)r * D_DIM);
    const float4* e2 = (const float4*)(emb + (size_t)jm * D_DIM);
    float d2 = 0.f;
#pragma unroll
    for (int i = 0; i < 4; i++) {
        int idx = lane + i * 32;
        float4 o = on[idx], b2 = __ldg(&e2[idx]);
        d2 = fmaf(o.x, b2.x, d2); d2 = fmaf(o.y, b2.y, d2);
        d2 = fmaf(o.z, b2.z, d2); d2 = fmaf(o.w, b2.w, d2);
    }
#pragma unroll
    for (int off = 16; off; off >>= 1)
        d2 += __shfl_xor_sync(0xffffffffu, d2, off);
    if (lane == 0) {
        float d1 = g_d1[r] * g_vinv[t];
        d2 *= g_vinv[jm];
        float df = fmaxf(GAMMA_F + d2 - d1, 0.f);
        g_diff[r] = (target[r] != *pad) ? df : 0.f;
    }
    __threadfence();
    __syncthreads();
    if (threadIdx.x == 0)
        s_last = (atomicAdd(&g_cnt, 1) == (int)gridDim.x - 1) ? 1 : 0;
    __syncthreads();
    if (!s_last) return;

    __shared__ float ssum[256];
    __shared__ float scnt[256];
    int tt = threadIdx.x;
    int p = *pad;
    float s = 0.f, c = 0.f;
    for (int rr = tt; rr < BS_ROWS; rr += 256) {
        s += g_diff[rr];
        c += (target[rr] != p) ? 1.f : 0.f;
    }
    ssum[tt] = s; scnt[tt] = c; __syncthreads();
    for (int off = 128; off; off >>= 1) {
        if (tt < off) { ssum[tt] += ssum[tt + off]; scnt[tt] += scnt[tt + off]; }
        __syncthreads();
    }
    if (tt == 0) {
        out[0] = ssum[0] / scnt[0];
        g_cnt = 0;   // self-reset for next graph replay
    }
}

// ---------------------------------------------------------------------------
extern "C" void kernel_launch(void* const* d_in, const int* in_sizes, int n_in,
                              void* d_out, int out_size) {
    const float* preds  = (const float*)d_in[0];
    const float* emb    = (const float*)d_in[1];
    const int*   target = (const int*)d_in[2];
    const int*   pad    = (const int*)d_in[3];

    cudaFuncSetAttribute(gemm_mma_kernel, cudaFuncAttributeMaxDynamicSharedMemorySize, SMEMSZ);

    pre_kernel<<<VBLKS + PBLKS, 256>>>(emb, preds, target);
    dim3 grid(BS_ROWS / MT, V_DIM / NT);   // (16, 200)
    gemm_mma_kernel<<<grid, 256, SMEMSZ>>>();
    finalize_reduce_kernel<<<BS_ROWS / 8, 256>>>(emb, target, pad, (float*)d_out);
}

// round 16
// speedup vs baseline: 1.0116x; 1.0038x over previous
#include <cuda_runtime.h>
#include <cuda_fp16.h>
#include <math.h>
#include <stdint.h>

// Problem constants
#define D_DIM   512
#define V_DIM   32000
#define BS_ROWS 2048
#define GAMMA_F 0.5f
#define EPS_F   1e-12f

// GEMM tiling: CTA 128x160, 8 warps (warp tile 32x80), 2 CTAs/SM
#define MT 128
#define NT 160
#define KC 64               // fp16 K per chunk (128 B rows)
#define NCHUNK 8            // 512 / 64
#define NSTAGE 3

// SMEM: 128B rows with XOR swizzle (chunk ^= row&7) -> conflict-free ldmatrix
#define ROWB   128
#define A_OFF  0
#define B_OFF  (MT * ROWB)               // 16384
#define STAGE  ((MT + NT) * ROWB)        // 36864
#define V_OFF  (NSTAGE * STAGE)          // 110592 : vinv staging (160 floats)
#define SMEMSZ (V_OFF + NT * 4)          // 111232

// ---------------------------------------------------------------------------
// Static scratch
// ---------------------------------------------------------------------------
__device__ __half g_qh[BS_ROWS * D_DIM];
__device__ __half g_eh[(size_t)V_DIM * D_DIM];
__device__ float              g_vinv[V_DIM];
__device__ float              g_outn[BS_ROWS * D_DIM];
__device__ float              g_d1[BS_ROWS];     // raw dot out_norm . emb[target]
__device__ unsigned long long g_best[BS_ROWS];
__device__ float              g_diff[BS_ROWS];
__device__ int                g_cnt;     // zero-initialized; self-resetting

// ---------------------------------------------------------------------------
// helpers
// ---------------------------------------------------------------------------
__device__ __forceinline__ uint32_t smem_u32(const void* p) {
    uint32_t a;
    asm("{ .reg .u64 t; cvta.to.shared.u64 t, %1; cvt.u32.u64 %0, t; }" : "=r"(a) : "l"(p));
    return a;
}
__device__ __forceinline__ void cp16(uint32_t dst, const void* src) {
    asm volatile("cp.async.cg.shared.global [%0], [%1], 16;" :: "r"(dst), "l"(src));
}
#define CP_COMMIT() asm volatile("cp.async.commit_group;" ::: "memory")
#define CP_WAIT1()  asm volatile("cp.async.wait_group 1;" ::: "memory")
#define CP_WAIT0()  asm volatile("cp.async.wait_group 0;" ::: "memory")

__device__ __forceinline__ void ldsm_x4(uint32_t addr, uint32_t& r0, uint32_t& r1,
                                        uint32_t& r2, uint32_t& r3) {
    asm volatile("ldmatrix.sync.aligned.m8n8.x4.shared.b16 {%0,%1,%2,%3}, [%4];"
                 : "=r"(r0), "=r"(r1), "=r"(r2), "=r"(r3) : "r"(addr));
}
__device__ __forceinline__ void mma16816(float* c, const uint32_t* a, const uint32_t* b) {
    asm volatile(
        "mma.sync.aligned.m16n8k16.row.col.f32.f16.f16.f32 "
        "{%0,%1,%2,%3}, {%4,%5,%6,%7}, {%8,%9}, {%0,%1,%2,%3};"
        : "+f"(c[0]), "+f"(c[1]), "+f"(c[2]), "+f"(c[3])
        : "r"(a[0]), "r"(a[1]), "r"(a[2]), "r"(a[3]), "r"(b[0]), "r"(b[1]));
}

// XOR swizzle: 16B chunk index within a 128B row, xored with row&7
__device__ __forceinline__ uint32_t swz(uint32_t row, uint32_t chunk) {
    return row * ROWB + ((chunk ^ (row & 7u)) << 4);
}

// pack 4 floats -> 4 halves in a uint2 (8B)
__device__ __forceinline__ uint2 pack_h4(float4 v) {
    __half2 lo = __halves2half2(__float2half_rn(v.x), __float2half_rn(v.y));
    __half2 hi = __halves2half2(__float2half_rn(v.z), __float2half_rn(v.w));
    uint2 r;
    r.x = *(uint32_t*)&lo;
    r.y = *(uint32_t*)&hi;
    return r;
}

// Monotone (score, idx) packing; bigger score wins, tie -> smaller index
__device__ __forceinline__ unsigned long long enc_key(float v, unsigned idx) {
    unsigned u = __float_as_uint(v);
    u = (u & 0x80000000u) ? ~u : (u | 0x80000000u);
    return ((unsigned long long)u << 32) | (unsigned long long)(0x7fffffffu - idx);
}
__device__ __forceinline__ int clamp_idx(int t) {
    t = t < 0 ? 0 : t;
    return t >= V_DIM ? V_DIM - 1 : t;
}

// ---------------------------------------------------------------------------
// Kernel 1 (merged): blocks [0,2000) = vocab pass (2 rows per warp, two
// load phases to cap live registers); blocks [2000,2512) = preds transpose
// + q build + d1 dot (ST=4). launch_bounds(256,7) -> 36 regs, 7 blocks/SM.
// ---------------------------------------------------------------------------
#define ST 4
#define VBLKS (V_DIM / 16)    // 2000 blocks * 8 warps * 2 rows = 32000
#define PBLKS (BS_ROWS / ST)  // 512
__global__ void __launch_bounds__(256, 7) pre_kernel(const float* __restrict__ emb,
                                                     const float* __restrict__ preds,
                                                     const int* __restrict__ target) {
    __shared__ float tile[D_DIM][ST + 1];   // 10240 B, prep role only
    __shared__ float part[64][ST + 1];
    __shared__ float inv_s[ST];
    __shared__ int   tgt_s[ST];
    __shared__ float dpart[8];              // 2 warps per row partials

    if (blockIdx.x < VBLKS) {
        // ------- vocab role: each warp handles rows r0, r0+1; 2 phases -------
        int warp = (blockIdx.x * 256 + threadIdx.x) >> 5;
        int lane = threadIdx.x & 31;
        int r0 = warp * 2;
        const float4* rowA = (const float4*)(emb + (size_t)r0 * D_DIM);
        const float4* rowB = (const float4*)(emb + (size_t)(r0 + 1) * D_DIM);

        float sa = 0.f, sb = 0.f;
#pragma unroll
        for (int ph = 0; ph < 2; ph++) {
            float4 va0 = __ldcs(&rowA[lane + 64 * ph]);
            float4 vb0 = __ldcs(&rowB[lane + 64 * ph]);
            float4 va1 = __ldcs(&rowA[lane + 32 + 64 * ph]);
            float4 vb1 = __ldcs(&rowB[lane + 32 + 64 * ph]);
            sa = fmaf(va0.x, va0.x, sa); sa = fmaf(va0.y, va0.y, sa);
            sa = fmaf(va0.z, va0.z, sa); sa = fmaf(va0.w, va0.w, sa);
            sa = fmaf(va1.x, va1.x, sa); sa = fmaf(va1.y, va1.y, sa);
            sa = fmaf(va1.z, va1.z, sa); sa = fmaf(va1.w, va1.w, sa);
            sb = fmaf(vb0.x, vb0.x, sb); sb = fmaf(vb0.y, vb0.y, sb);
            sb = fmaf(vb0.z, vb0.z, sb); sb = fmaf(vb0.w, vb0.w, sb);
            sb = fmaf(vb1.x, vb1.x, sb); sb = fmaf(vb1.y, vb1.y, sb);
            sb = fmaf(vb1.z, vb1.z, sb); sb = fmaf(vb1.w, vb1.w, sb);
            size_t e0 = (size_t)r0 * D_DIM + (lane + 64 * ph) * 4;
            size_t e1 = (size_t)r0 * D_DIM + (lane + 32 + 64 * ph) * 4;
            *(uint2*)(g_eh + e0)         = pack_h4(va0);
            *(uint2*)(g_eh + e0 + D_DIM) = pack_h4(vb0);
            *(uint2*)(g_eh + e1)         = pack_h4(va1);
            *(uint2*)(g_eh + e1 + D_DIM) = pack_h4(vb1);
        }
#pragma unroll
        for (int off = 16; off; off >>= 1) {
            sa += __shfl_xor_sync(0xffffffffu, sa, off);
            sb += __shfl_xor_sync(0xffffffffu, sb, off);
        }
        if (lane == 0) {
            g_vinv[r0]     = 1.f / fmaxf(sqrtf(sa), EPS_F);
            g_vinv[r0 + 1] = 1.f / fmaxf(sqrtf(sb), EPS_F);
        }
        return;
    }

    // ------- prep role: single global pass, smem-staged transpose -------
    int blk = blockIdx.x - VBLKS;       // 0..511
    int b   = blk >> 7;                 // 4 batches x 128 s-tiles
    int s0  = (blk & 127) * ST;
    int t   = threadIdx.x;
    const float* P = preds + (size_t)b * D_DIM * 512 + s0;

    int ss = t & 3, dr = t >> 2;        // ss 0..3, dr 0..63
#pragma unroll
    for (int d0 = 0; d0 < D_DIM; d0 += 64)
        tile[d0 + dr][ss] = P[(size_t)(d0 + dr) * 512 + ss];
    __syncthreads();

    float acc = 0.f;
#pragma unroll
    for (int d0 = 0; d0 < D_DIM; d0 += 64)
        { float x = tile[d0 + dr][ss]; acc = fmaf(x, x, acc); }
    part[dr][ss] = acc;
    __syncthreads();
    if (t < ST) {
        float n = 0.f;
#pragma unroll
        for (int i = 0; i < 64; i++) n += part[i][t];
        inv_s[t] = 1.f / fmaxf(sqrtf(n), EPS_F);
        int r = b * 512 + s0 + t;
        tgt_s[t] = clamp_idx(target[r]);
        g_best[r] = 0ull;
    }
    __syncthreads();

    int ss2  = t >> 6;                  // 0..3
    int dcol = (t & 63) * 4;            // 0..252 step 4
    float inv = inv_s[ss2];
    int r = b * 512 + s0 + ss2;
    const float* erow = emb + (size_t)tgt_s[ss2] * D_DIM;
    float dot = 0.f;
#pragma unroll
    for (int d0 = 0; d0 < D_DIM; d0 += 256) {
        float4 o;
        __half hq[4];
        float* ov = &o.x;
#pragma unroll
        for (int j = 0; j < 4; j++) {
            float e  = erow[d0 + dcol + j];
            float on = tile[d0 + dcol + j][ss2] * inv;
            ov[j] = on;
            hq[j] = __float2half_rn(on - e);
            dot = fmaf(on, e, dot);
        }
        *(float4*)(g_outn + (size_t)r * D_DIM + d0 + dcol) = o;
        *(__half2*)(g_qh + (size_t)r * D_DIM + d0 + dcol)     = __halves2half2(hq[0], hq[1]);
        *(__half2*)(g_qh + (size_t)r * D_DIM + d0 + dcol + 2) = __halves2half2(hq[2], hq[3]);
    }
    // reduce dot across the 64 threads (2 warps) of row ss2
#pragma unroll
    for (int off = 16; off; off >>= 1) dot += __shfl_xor_sync(0xffffffffu, dot, off);
    if ((t & 31) == 0) dpart[t >> 5] = dot;
    __syncthreads();
    if (t < ST) g_d1[b * 512 + s0 + t] = dpart[2 * t] + dpart[2 * t + 1];
}

// ---------------------------------------------------------------------------
// Kernel 2: fp16 mma.sync GEMM, 3-stage cp.async (1 barrier/chunk), 2 CTAs/SM,
// XOR-swizzled SMEM, vinv prefetched pre-loop, fused argmax epilogue.
// CTA 128x160, warp tile 32x80.
// ---------------------------------------------------------------------------
__global__ void __launch_bounds__(256, 2) gemm_mma_kernel() {
    extern __shared__ char smem[];
    const uint32_t sb = smem_u32(smem);
    const int tid  = threadIdx.x;
    const int wid  = tid >> 5;
    const int lane = tid & 31;
    const int mblk = blockIdx.x * MT;
    const int nblk = blockIdx.y * NT;
    const int warp_m = (wid & 3) * 32;      // 4 warps along M
    const int warp_n = (wid >> 2) * 80;     // 2 warps along N

    const __half* Aqh = g_qh + (size_t)mblk * D_DIM;
    const __half* Beh = g_eh + (size_t)nblk * D_DIM;

    if (tid < NT) ((float*)(smem + V_OFF))[tid] = g_vinv[nblk + tid];

    auto load_chunk = [&](int slot, int ch) {
        int kc = ch * KC;
        uint32_t st = sb + slot * STAGE;
#pragma unroll
        for (int i = 0; i < 4; i++) {
            int s = tid + i * 256;
            int row = s >> 3, c = s & 7;
            cp16(st + A_OFF + swz(row, c), Aqh + (size_t)row * D_DIM + kc + c * 8);
        }
#pragma unroll
        for (int i = 0; i < 5; i++) {
            int s = tid + i * 256;
            int row = s >> 3, c = s & 7;
            cp16(st + B_OFF + swz(row, c), Beh + (size_t)row * D_DIM + kc + c * 8);
        }
    };

    float acc[2][10][4];
#pragma unroll
    for (int i = 0; i < 2; i++)
#pragma unroll
        for (int j = 0; j < 10; j++)
#pragma unroll
            for (int k = 0; k < 4; k++) acc[i][j][k] = 0.f;

    load_chunk(0, 0); CP_COMMIT();
    load_chunk(1, 1); CP_COMMIT();

    for (int it = 0; it < NCHUNK; it++) {
        if (it + 1 < NCHUNK) { CP_WAIT1(); } else { CP_WAIT0(); }
        __syncthreads();

        if (it + 2 < NCHUNK) {
            load_chunk((it + 2) % NSTAGE, it + 2);
            CP_COMMIT();
        }

        uint32_t st  = sb + (it % NSTAGE) * STAGE;
        uint32_t sa  = st + A_OFF;
        uint32_t sbm = st + B_OFF;
#pragma unroll
        for (int ks = 0; ks < 4; ks++) {
            int k = ks * 16;
            uint32_t a[2][4];
#pragma unroll
            for (int mi = 0; mi < 2; mi++) {
                int row = warp_m + mi * 16 + (lane & 15);
                int kch = (k >> 3) + (lane >> 4);
                ldsm_x4(sa + swz(row, kch), a[mi][0], a[mi][1], a[mi][2], a[mi][3]);
            }
#pragma unroll
            for (int bj = 0; bj < 5; bj++) {
                uint32_t b0[2], b1[2];
                int n   = warp_n + bj * 16 + (lane & 7) + ((lane >> 4) & 1) * 8;
                int kch = (k >> 3) + ((lane >> 3) & 1);
                ldsm_x4(sbm + swz(n, kch), b0[0], b0[1], b1[0], b1[1]);
#pragma unroll
                for (int mi = 0; mi < 2; mi++) {
                    mma16816(acc[mi][bj * 2],     a[mi], b0);
                    mma16816(acc[mi][bj * 2 + 1], a[mi], b1);
                }
            }
        }
    }
    const float* vin = (const float*)(smem + V_OFF);

#pragma unroll
    for (int mi = 0; mi < 2; mi++) {
        float bv0 = -1e30f, bv1 = -1e30f;
        int   bj0 = 0,      bj1 = 0;
#pragma unroll
        for (int nj = 0; nj < 10; nj++) {
            int c0 = warp_n + nj * 8 + 2 * (lane & 3);
            float v00 = acc[mi][nj][0] * vin[c0];
            float v01 = acc[mi][nj][1] * vin[c0 + 1];
            float v10 = acc[mi][nj][2] * vin[c0];
            float v11 = acc[mi][nj][3] * vin[c0 + 1];
            if (v00 > bv0) { bv0 = v00; bj0 = c0; }
            if (v01 > bv0) { bv0 = v01; bj0 = c0 + 1; }
            if (v10 > bv1) { bv1 = v10; bj1 = c0; }
            if (v11 > bv1) { bv1 = v11; bj1 = c0 + 1; }
        }
#pragma unroll
        for (int off = 1; off < 4; off <<= 1) {
            float o0 = __shfl_xor_sync(0xffffffffu, bv0, off);
            int   j0 = __shfl_xor_sync(0xffffffffu, bj0, off);
            float o1 = __shfl_xor_sync(0xffffffffu, bv1, off);
            int   j1 = __shfl_xor_sync(0xffffffffu, bj1, off);
            if (o0 > bv0 || (o0 == bv0 && j0 < bj0)) { bv0 = o0; bj0 = j0; }
            if (o1 > bv1 || (o1 == bv1 && j1 < bj1)) { bv1 = o1; bj1 = j1; }
        }
        if ((lane & 3) == 0) {
            int r0 = mblk + warp_m + mi * 16 + (lane >> 2);
            atomicMax(&g_best[r0],     enc_key(bv0, (unsigned)(nblk + bj0)));
            atomicMax(&g_best[r0 + 8], enc_key(bv1, (unsigned)(nblk + bj1)));
        }
    }
}

// ---------------------------------------------------------------------------
// Kernel 3: per-row hinge (warp/row; d1 precomputed in prep) + last-block
// scalar reduction. Self-resetting counter (graph-replay safe).
// ---------------------------------------------------------------------------
__global__ void __launch_bounds__(256) finalize_reduce_kernel(
        const float* __restrict__ emb,
        const int* __restrict__ target,
        const int* __restrict__ pad,
        float* __restrict__ out) {
    __shared__ int s_last;
    int r    = blockIdx.x * 8 + (threadIdx.x >> 5);
    int lane = threadIdx.x & 31;
    int t = clamp_idx(target[r]);
    unsigned long long key = g_best[r];
    int jm = clamp_idx((int)(0x7fffffffu - (unsigned)(key & 0xffffffffu)));

    const float4* on = (const float4*)(g_outn + (size_t)r * D_DIM);
    const float4* e2 = (const float4*)(emb + (size_t)jm * D_DIM);
    float d2 = 0.f;
#pragma unroll
    for (int i = 0; i < 4; i++) {
        int idx = lane + i * 32;
        float4 o = on[idx], b2 = __ldg(&e2[idx]);
        d2 = fmaf(o.x, b2.x, d2); d2 = fmaf(o.y, b2.y, d2);
        d2 = fmaf(o.z, b2.z, d2); d2 = fmaf(o.w, b2.w, d2);
    }
#pragma unroll
    for (int off = 16; off; off >>= 1)
        d2 += __shfl_xor_sync(0xffffffffu, d2, off);
    if (lane == 0) {
        float d1 = g_d1[r] * g_vinv[t];
        d2 *= g_vinv[jm];
        float df = fmaxf(GAMMA_F + d2 - d1, 0.f);
        g_diff[r] = (target[r] != *pad) ? df : 0.f;
    }
    __threadfence();
    __syncthreads();
    if (threadIdx.x == 0)
        s_last = (atomicAdd(&g_cnt, 1) == (int)gridDim.x - 1) ? 1 : 0;
    __syncthreads();
    if (!s_last) return;

    __shared__ float ssum[256];
    __shared__ float scnt[256];
    int tt = threadIdx.x;
    int p = *pad;
    float s = 0.f, c = 0.f;
    for (int rr = tt; rr < BS_ROWS; rr += 256) {
        s += g_diff[rr];
        c += (target[rr] != p) ? 1.f : 0.f;
    }
    ssum[tt] = s; scnt[tt] = c; __syncthreads();
    for (int off = 128; off; off >>= 1) {
        if (tt < off) { ssum[tt] += ssum[tt + off]; scnt[tt] += scnt[tt + off]; }
        __syncthreads();
    }
    if (tt == 0) {
        out[0] = ssum[0] / scnt[0];
        g_cnt = 0;   // self-reset for next graph replay
    }
}

// ---------------------------------------------------------------------------
extern "C" void kernel_launch(void* const* d_in, const int* in_sizes, int n_in,
                              void* d_out, int out_size) {
    const float* preds  = (const float*)d_in[0];
    const float* emb    = (const float*)d_in[1];
    const int*   target = (const int*)d_in[2];
    const int*   pad    = (const int*)d_in[3];

    cudaFuncSetAttribute(gemm_mma_kernel, cudaFuncAttributeMaxDynamicSharedMemorySize, SMEMSZ);

    pre_kernel<<<VBLKS + PBLKS, 256>>>(emb, preds, target);
    dim3 grid(BS_ROWS / MT, V_DIM / NT);   // (16, 200)
    gemm_mma_kernel<<<grid, 256, SMEMSZ>>>();
    finalize_reduce_kernel<<<BS_ROWS / 8, 256>>>(emb, target, pad, (float*)d_out);
}

// round 17
// speedup vs baseline: 1.0192x; 1.0075x over previous
#include <cuda_runtime.h>
#include <cuda_fp16.h>
#include <math.h>
#include <stdint.h>

// Problem constants
#define D_DIM   512
#define V_DIM   32000
#define BS_ROWS 2048
#define GAMMA_F 0.5f
#define EPS_F   1e-12f

// GEMM tiling: CTA 128x160, 8 warps (warp tile 32x80), 2 CTAs/SM
#define MT 128
#define NT 160
#define KC 64               // fp16 K per chunk (128 B rows)
#define NCHUNK 8            // 512 / 64
#define NSTAGE 3

// SMEM: 128B rows with XOR swizzle (chunk ^= row&7) -> conflict-free ldmatrix
#define ROWB   128
#define A_OFF  0
#define B_OFF  (MT * ROWB)               // 16384
#define STAGE  ((MT + NT) * ROWB)        // 36864
#define V_OFF  (NSTAGE * STAGE)          // 110592 : vinv staging (160 floats)
#define SMEMSZ (V_OFF + NT * 4)          // 111232

// PDL: producer signals dependents may roll out; consumer waits before
// touching producer outputs.
#define PDL_LAUNCH() asm volatile("griddepcontrol.launch_dependents;" ::: "memory")
#define PDL_WAIT()   asm volatile("griddepcontrol.wait;" ::: "memory")

// ---------------------------------------------------------------------------
// Static scratch
// ---------------------------------------------------------------------------
__device__ __half g_qh[BS_ROWS * D_DIM];
__device__ __half g_eh[(size_t)V_DIM * D_DIM];
__device__ float              g_vinv[V_DIM];
__device__ float              g_outn[BS_ROWS * D_DIM];
__device__ float              g_d1[BS_ROWS];     // raw dot out_norm . emb[target]
__device__ unsigned long long g_best[BS_ROWS];
__device__ float              g_diff[BS_ROWS];
__device__ int                g_cnt;     // zero-initialized; self-resetting

// ---------------------------------------------------------------------------
// helpers
// ---------------------------------------------------------------------------
__device__ __forceinline__ uint32_t smem_u32(const void* p) {
    uint32_t a;
    asm("{ .reg .u64 t; cvta.to.shared.u64 t, %1; cvt.u32.u64 %0, t; }" : "=r"(a) : "l"(p));
    return a;
}
__device__ __forceinline__ void cp16(uint32_t dst, const void* src) {
    asm volatile("cp.async.cg.shared.global [%0], [%1], 16;" :: "r"(dst), "l"(src));
}
#define CP_COMMIT() asm volatile("cp.async.commit_group;" ::: "memory")
#define CP_WAIT1()  asm volatile("cp.async.wait_group 1;" ::: "memory")
#define CP_WAIT0()  asm volatile("cp.async.wait_group 0;" ::: "memory")

__device__ __forceinline__ void ldsm_x4(uint32_t addr, uint32_t& r0, uint32_t& r1,
                                        uint32_t& r2, uint32_t& r3) {
    asm volatile("ldmatrix.sync.aligned.m8n8.x4.shared.b16 {%0,%1,%2,%3}, [%4];"
                 : "=r"(r0), "=r"(r1), "=r"(r2), "=r"(r3) : "r"(addr));
}
__device__ __forceinline__ void mma16816(float* c, const uint32_t* a, const uint32_t* b) {
    asm volatile(
        "mma.sync.aligned.m16n8k16.row.col.f32.f16.f16.f32 "
        "{%0,%1,%2,%3}, {%4,%5,%6,%7}, {%8,%9}, {%0,%1,%2,%3};"
        : "+f"(c[0]), "+f"(c[1]), "+f"(c[2]), "+f"(c[3])
        : "r"(a[0]), "r"(a[1]), "r"(a[2]), "r"(a[3]), "r"(b[0]), "r"(b[1]));
}

// XOR swizzle: 16B chunk index within a 128B row, xored with row&7
__device__ __forceinline__ uint32_t swz(uint32_t row, uint32_t chunk) {
    return row * ROWB + ((chunk ^ (row & 7u)) << 4);
}

// pack 4 floats -> 4 halves in a uint2 (8B)
__device__ __forceinline__ uint2 pack_h4(float4 v) {
    __half2 lo = __halves2half2(__float2half_rn(v.x), __float2half_rn(v.y));
    __half2 hi = __halves2half2(__float2half_rn(v.z), __float2half_rn(v.w));
    uint2 r;
    r.x = *(uint32_t*)&lo;
    r.y = *(uint32_t*)&hi;
    return r;
}

// Monotone (score, idx) packing; bigger score wins, tie -> smaller index
__device__ __forceinline__ unsigned long long enc_key(float v, unsigned idx) {
    unsigned u = __float_as_uint(v);
    u = (u & 0x80000000u) ? ~u : (u | 0x80000000u);
    return ((unsigned long long)u << 32) | (unsigned long long)(0x7fffffffu - idx);
}
__device__ __forceinline__ int clamp_idx(int t) {
    t = t < 0 ? 0 : t;
    return t >= V_DIM ? V_DIM - 1 : t;
}

// ---------------------------------------------------------------------------
// Kernel 1 (merged): blocks [0,2000) = vocab pass (2 rows per warp, two
// load phases); blocks [2000,2512) = preds transpose + q build + d1 dot.
// ---------------------------------------------------------------------------
#define ST 4
#define VBLKS (V_DIM / 16)    // 2000
#define PBLKS (BS_ROWS / ST)  // 512
__global__ void __launch_bounds__(256, 7) pre_kernel(const float* __restrict__ emb,
                                                     const float* __restrict__ preds,
                                                     const int* __restrict__ target) {
    __shared__ float tile[D_DIM][ST + 1];
    __shared__ float part[64][ST + 1];
    __shared__ float inv_s[ST];
    __shared__ int   tgt_s[ST];
    __shared__ float dpart[8];

    if (blockIdx.x < VBLKS) {
        int warp = (blockIdx.x * 256 + threadIdx.x) >> 5;
        int lane = threadIdx.x & 31;
        int r0 = warp * 2;
        const float4* rowA = (const float4*)(emb + (size_t)r0 * D_DIM);
        const float4* rowB = (const float4*)(emb + (size_t)(r0 + 1) * D_DIM);

        float sa = 0.f, sb = 0.f;
#pragma unroll
        for (int ph = 0; ph < 2; ph++) {
            float4 va0 = __ldcs(&rowA[lane + 64 * ph]);
            float4 vb0 = __ldcs(&rowB[lane + 64 * ph]);
            float4 va1 = __ldcs(&rowA[lane + 32 + 64 * ph]);
            float4 vb1 = __ldcs(&rowB[lane + 32 + 64 * ph]);
            sa = fmaf(va0.x, va0.x, sa); sa = fmaf(va0.y, va0.y, sa);
            sa = fmaf(va0.z, va0.z, sa); sa = fmaf(va0.w, va0.w, sa);
            sa = fmaf(va1.x, va1.x, sa); sa = fmaf(va1.y, va1.y, sa);
            sa = fmaf(va1.z, va1.z, sa); sa = fmaf(va1.w, va1.w, sa);
            sb = fmaf(vb0.x, vb0.x, sb); sb = fmaf(vb0.y, vb0.y, sb);
            sb = fmaf(vb0.z, vb0.z, sb); sb = fmaf(vb0.w, vb0.w, sb);
            sb = fmaf(vb1.x, vb1.x, sb); sb = fmaf(vb1.y, vb1.y, sb);
            sb = fmaf(vb1.z, vb1.z, sb); sb = fmaf(vb1.w, vb1.w, sb);
            size_t e0 = (size_t)r0 * D_DIM + (lane + 64 * ph) * 4;
            size_t e1 = (size_t)r0 * D_DIM + (lane + 32 + 64 * ph) * 4;
            *(uint2*)(g_eh + e0)         = pack_h4(va0);
            *(uint2*)(g_eh + e0 + D_DIM) = pack_h4(vb0);
            *(uint2*)(g_eh + e1)         = pack_h4(va1);
            *(uint2*)(g_eh + e1 + D_DIM) = pack_h4(vb1);
        }
#pragma unroll
        for (int off = 16; off; off >>= 1) {
            sa += __shfl_xor_sync(0xffffffffu, sa, off);
            sb += __shfl_xor_sync(0xffffffffu, sb, off);
        }
        if (lane == 0) {
            g_vinv[r0]     = 1.f / fmaxf(sqrtf(sa), EPS_F);
            g_vinv[r0 + 1] = 1.f / fmaxf(sqrtf(sb), EPS_F);
        }
        PDL_LAUNCH();
        return;
    }

    int blk = blockIdx.x - VBLKS;       // 0..511
    int b   = blk >> 7;
    int s0  = (blk & 127) * ST;
    int t   = threadIdx.x;
    const float* P = preds + (size_t)b * D_DIM * 512 + s0;

    int ss = t & 3, dr = t >> 2;
#pragma unroll
    for (int d0 = 0; d0 < D_DIM; d0 += 64)
        tile[d0 + dr][ss] = P[(size_t)(d0 + dr) * 512 + ss];
    __syncthreads();

    float acc = 0.f;
#pragma unroll
    for (int d0 = 0; d0 < D_DIM; d0 += 64)
        { float x = tile[d0 + dr][ss]; acc = fmaf(x, x, acc); }
    part[dr][ss] = acc;
    __syncthreads();
    if (t < ST) {
        float n = 0.f;
#pragma unroll
        for (int i = 0; i < 64; i++) n += part[i][t];
        inv_s[t] = 1.f / fmaxf(sqrtf(n), EPS_F);
        int r = b * 512 + s0 + t;
        tgt_s[t] = clamp_idx(target[r]);
        g_best[r] = 0ull;
    }
    __syncthreads();

    int ss2  = t >> 6;
    int dcol = (t & 63) * 4;
    float inv = inv_s[ss2];
    int r = b * 512 + s0 + ss2;
    const float* erow = emb + (size_t)tgt_s[ss2] * D_DIM;
    float dot = 0.f;
#pragma unroll
    for (int d0 = 0; d0 < D_DIM; d0 += 256) {
        float4 o;
        __half hq[4];
        float* ov = &o.x;
#pragma unroll
        for (int j = 0; j < 4; j++) {
            float e  = erow[d0 + dcol + j];
            float on = tile[d0 + dcol + j][ss2] * inv;
            ov[j] = on;
            hq[j] = __float2half_rn(on - e);
            dot = fmaf(on, e, dot);
        }
        *(float4*)(g_outn + (size_t)r * D_DIM + d0 + dcol) = o;
        *(__half2*)(g_qh + (size_t)r * D_DIM + d0 + dcol)     = __halves2half2(hq[0], hq[1]);
        *(__half2*)(g_qh + (size_t)r * D_DIM + d0 + dcol + 2) = __halves2half2(hq[2], hq[3]);
    }
#pragma unroll
    for (int off = 16; off; off >>= 1) dot += __shfl_xor_sync(0xffffffffu, dot, off);
    if ((t & 31) == 0) dpart[t >> 5] = dot;
    __syncthreads();
    if (t < ST) g_d1[b * 512 + s0 + t] = dpart[2 * t] + dpart[2 * t + 1];
    PDL_LAUNCH();
}

// ---------------------------------------------------------------------------
// Kernel 2: fp16 mma.sync GEMM (R13 config) + PDL wait/arm.
// ---------------------------------------------------------------------------
__global__ void __launch_bounds__(256, 2) gemm_mma_kernel() {
    extern __shared__ char smem[];
    const uint32_t sb = smem_u32(smem);
    const int tid  = threadIdx.x;
    const int wid  = tid >> 5;
    const int lane = tid & 31;
    const int mblk = blockIdx.x * MT;
    const int nblk = blockIdx.y * NT;
    const int warp_m = (wid & 3) * 32;
    const int warp_n = (wid >> 2) * 80;

    const __half* Aqh = g_qh + (size_t)mblk * D_DIM;
    const __half* Beh = g_eh + (size_t)nblk * D_DIM;

    PDL_WAIT();   // pre_kernel outputs (g_qh/g_eh/g_vinv/g_best) must be ready

    if (tid < NT) ((float*)(smem + V_OFF))[tid] = g_vinv[nblk + tid];

    auto load_chunk = [&](int slot, int ch) {
        int kc = ch * KC;
        uint32_t st = sb + slot * STAGE;
#pragma unroll
        for (int i = 0; i < 4; i++) {
            int s = tid + i * 256;
            int row = s >> 3, c = s & 7;
            cp16(st + A_OFF + swz(row, c), Aqh + (size_t)row * D_DIM + kc + c * 8);
        }
#pragma unroll
        for (int i = 0; i < 5; i++) {
            int s = tid + i * 256;
            int row = s >> 3, c = s & 7;
            cp16(st + B_OFF + swz(row, c), Beh + (size_t)row * D_DIM + kc + c * 8);
        }
    };

    float acc[2][10][4];
#pragma unroll
    for (int i = 0; i < 2; i++)
#pragma unroll
        for (int j = 0; j < 10; j++)
#pragma unroll
            for (int k = 0; k < 4; k++) acc[i][j][k] = 0.f;

    load_chunk(0, 0); CP_COMMIT();
    load_chunk(1, 1); CP_COMMIT();

    for (int it = 0; it < NCHUNK; it++) {
        if (it + 1 < NCHUNK) { CP_WAIT1(); } else { CP_WAIT0(); }
        __syncthreads();

        if (it + 2 < NCHUNK) {
            load_chunk((it + 2) % NSTAGE, it + 2);
            CP_COMMIT();
        }

        uint32_t st  = sb + (it % NSTAGE) * STAGE;
        uint32_t sa  = st + A_OFF;
        uint32_t sbm = st + B_OFF;
#pragma unroll
        for (int ks = 0; ks < 4; ks++) {
            int k = ks * 16;
            uint32_t a[2][4];
#pragma unroll
            for (int mi = 0; mi < 2; mi++) {
                int row = warp_m + mi * 16 + (lane & 15);
                int kch = (k >> 3) + (lane >> 4);
                ldsm_x4(sa + swz(row, kch), a[mi][0], a[mi][1], a[mi][2], a[mi][3]);
            }
#pragma unroll
            for (int bj = 0; bj < 5; bj++) {
                uint32_t b0[2], b1[2];
                int n   = warp_n + bj * 16 + (lane & 7) + ((lane >> 4) & 1) * 8;
                int kch = (k >> 3) + ((lane >> 3) & 1);
                ldsm_x4(sbm + swz(n, kch), b0[0], b0[1], b1[0], b1[1]);
#pragma unroll
                for (int mi = 0; mi < 2; mi++) {
                    mma16816(acc[mi][bj * 2],     a[mi], b0);
                    mma16816(acc[mi][bj * 2 + 1], a[mi], b1);
                }
            }
        }
    }
    const float* vin = (const float*)(smem + V_OFF);

#pragma unroll
    for (int mi = 0; mi < 2; mi++) {
        float bv0 = -1e30f, bv1 = -1e30f;
        int   bj0 = 0,      bj1 = 0;
#pragma unroll
        for (int nj = 0; nj < 10; nj++) {
            int c0 = warp_n + nj * 8 + 2 * (lane & 3);
            float v00 = acc[mi][nj][0] * vin[c0];
            float v01 = acc[mi][nj][1] * vin[c0 + 1];
            float v10 = acc[mi][nj][2] * vin[c0];
            float v11 = acc[mi][nj][3] * vin[c0 + 1];
            if (v00 > bv0) { bv0 = v00; bj0 = c0; }
            if (v01 > bv0) { bv0 = v01; bj0 = c0 + 1; }
            if (v10 > bv1) { bv1 = v10; bj1 = c0; }
            if (v11 > bv1) { bv1 = v11; bj1 = c0 + 1; }
        }
#pragma unroll
        for (int off = 1; off < 4; off <<= 1) {
            float o0 = __shfl_xor_sync(0xffffffffu, bv0, off);
            int   j0 = __shfl_xor_sync(0xffffffffu, bj0, off);
            float o1 = __shfl_xor_sync(0xffffffffu, bv1, off);
            int   j1 = __shfl_xor_sync(0xffffffffu, bj1, off);
            if (o0 > bv0 || (o0 == bv0 && j0 < bj0)) { bv0 = o0; bj0 = j0; }
            if (o1 > bv1 || (o1 == bv1 && j1 < bj1)) { bv1 = o1; bj1 = j1; }
        }
        if ((lane & 3) == 0) {
            int r0 = mblk + warp_m + mi * 16 + (lane >> 2);
            atomicMax(&g_best[r0],     enc_key(bv0, (unsigned)(nblk + bj0)));
            atomicMax(&g_best[r0 + 8], enc_key(bv1, (unsigned)(nblk + bj1)));
        }
    }
    PDL_LAUNCH();
}

// ---------------------------------------------------------------------------
// Kernel 3: per-row hinge (warp/row; d1 precomputed) + last-block reduction.
// ---------------------------------------------------------------------------
__global__ void __launch_bounds__(256) finalize_reduce_kernel(
        const float* __restrict__ emb,
        const int* __restrict__ target,
        const int* __restrict__ pad,
        float* __restrict__ out) {
    __shared__ int s_last;
    int r    = blockIdx.x * 8 + (threadIdx.x >> 5);
    int lane = threadIdx.x & 31;
    int t = clamp_idx(target[r]);

    PDL_WAIT();   // g_best must be final

    unsigned long long key = g_best[r];
    int jm = clamp_idx((int)(0x7fffffffu - (unsigned)(key & 0xffffffffu)));

    const float4* on = (const float4*)(g_outn + (size_t)r * D_DIM);
    const float4* e2 = (const float4*)(emb + (size_t)jm * D_DIM);
    float d2 = 0.f;
#pragma unroll
    for (int i = 0; i < 4; i++) {
        int idx = lane + i * 32;
        float4 o = on[idx], b2 = __ldg(&e2[idx]);
        d2 = fmaf(o.x, b2.x, d2); d2 = fmaf(o.y, b2.y, d2);
        d2 = fmaf(o.z, b2.z, d2); d2 = fmaf(o.w, b2.w, d2);
    }
#pragma unroll
    for (int off = 16; off; off >>= 1)
        d2 += __shfl_xor_sync(0xffffffffu, d2, off);
    if (lane == 0) {
        float d1 = g_d1[r] * g_vinv[t];
        d2 *= g_vinv[jm];
        float df = fmaxf(GAMMA_F + d2 - d1, 0.f);
        g_diff[r] = (target[r] != *pad) ? df : 0.f;
    }
    __threadfence();
    __syncthreads();
    if (threadIdx.x == 0)
        s_last = (atomicAdd(&g_cnt, 1) == (int)gridDim.x - 1) ? 1 : 0;
    __syncthreads();
    if (!s_last) return;

    __shared__ float ssum[256];
    __shared__ float scnt[256];
    int tt = threadIdx.x;
    int p = *pad;
    float s = 0.f, c = 0.f;
    for (int rr = tt; rr < BS_ROWS; rr += 256) {
        s += g_diff[rr];
        c += (target[rr] != p) ? 1.f : 0.f;
    }
    ssum[tt] = s; scnt[tt] = c; __syncthreads();
    for (int off = 128; off; off >>= 1) {
        if (tt < off) { ssum[tt] += ssum[tt + off]; scnt[tt] += scnt[tt + off]; }
        __syncthreads();
    }
    if (tt == 0) {
        out[0] = ssum[0] / scnt[0];
        g_cnt = 0;   // self-reset for next graph replay
    }
}

// ---------------------------------------------------------------------------
extern "C" void kernel_launch(void* const* d_in, const int* in_sizes, int n_in,
                              void* d_out, int out_size) {
    const float* preds  = (const float*)d_in[0];
    const float* emb    = (const float*)d_in[1];
    const int*   target = (const int*)d_in[2];
    const int*   pad    = (const int*)d_in[3];
    float*       outp   = (float*)d_out;

    cudaFuncSetAttribute(gemm_mma_kernel, cudaFuncAttributeMaxDynamicSharedMemorySize, SMEMSZ);

    pre_kernel<<<VBLKS + PBLKS, 256>>>(emb, preds, target);

    // GEMM with programmatic dependent launch on pre_kernel
    {
        cudaLaunchConfig_t cfg = {};
        cfg.gridDim = dim3(BS_ROWS / MT, V_DIM / NT, 1);   // (16, 200)
        cfg.blockDim = dim3(256, 1, 1);
        cfg.dynamicSmemBytes = SMEMSZ;
        cudaLaunchAttribute attr[1];
        attr[0].id = cudaLaunchAttributeProgrammaticStreamSerialization;
        attr[0].val.programmaticStreamSerializationAllowed = 1;
        cfg.attrs = attr;
        cfg.numAttrs = 1;
        cudaLaunchKernelEx(&cfg, gemm_mma_kernel);
    }

    // finalize with PDL on the GEMM
    {
        cudaLaunchConfig_t cfg = {};
        cfg.gridDim = dim3(BS_ROWS / 8, 1, 1);
        cfg.blockDim = dim3(256, 1, 1);
        cfg.dynamicSmemBytes = 0;
        cudaLaunchAttribute attr[1];
        attr[0].id = cudaLaunchAttributeProgrammaticStreamSerialization;
        attr[0].val.programmaticStreamSerializationAllowed = 1;
        cfg.attrs = attr;
        cfg.numAttrs = 1;
        cudaLaunchKernelEx(&cfg, finalize_reduce_kernel, emb, target, pad, outp);
    }
}